// round 14
// baseline (speedup 1.0000x reference)
#include <cuda_runtime.h>
#include <cuda_bf16.h>
#include <math.h>
#include <stdint.h>

#define NN 50000
#define NE 1600000
#define NF 256
#define NH 128
#define NC 40

// ---------------- scratch (no allocations allowed) ----------------
__device__ float g_dinv[NN];    // main-stream product
__device__ int   g_deg[NN];     // main-stream histogram (self-loop incl.)
__device__ int   g_cnt[NN];     // side-stream histogram
__device__ int   g_base[NN];
__device__ int   g_cur[NN];
__device__ int   g_eidx[NE];
__device__ __align__(16) float g_G1[(size_t)NN * NH];   // dinv * (X @ W1)
__device__ __align__(16) float g_H1[(size_t)NN * NH];
__device__ __align__(16) float g_G2[(size_t)NN * NC];   // dinv * (H1 @ W2)
__device__ __align__(16) __nv_bfloat16 g_W1h[NF * NH];  // transposed: [n][k] = n*NF+k
__device__ __align__(16) __nv_bfloat16 g_W1l[NF * NH];

static __device__ __forceinline__ uint32_t pkbf(__nv_bfloat16 a, __nv_bfloat16 b) {
    uint16_t ua = *(uint16_t*)&a, ub = *(uint16_t*)&b;
    return (uint32_t)ua | ((uint32_t)ub << 16);
}

static __device__ __forceinline__ void hmma16816(float* c, uint32_t a0, uint32_t a1,
                                                 uint32_t a2, uint32_t a3,
                                                 uint32_t b0, uint32_t b1) {
    asm volatile("mma.sync.aligned.m16n8k16.row.col.f32.bf16.bf16.f32 "
                 "{%0,%1,%2,%3}, {%4,%5,%6,%7}, {%8,%9}, {%0,%1,%2,%3};"
                 : "+f"(c[0]), "+f"(c[1]), "+f"(c[2]), "+f"(c[3])
                 : "r"(a0), "r"(a1), "r"(a2), "r"(a3), "r"(b0), "r"(b1));
}

// ================= MAIN-STREAM degree/dinv chain =================
__global__ void k_zerodeg() {
    int v = blockIdx.x * 256 + threadIdx.x;
    if (v < NN) g_deg[v] = 1;            // self-loop
}
__global__ void k_histdeg(const int* __restrict__ dst) {
    int t = blockIdx.x * 256 + threadIdx.x;
    if (t < NE / 4) {
        int4 d = ((const int4*)dst)[t];
        atomicAdd(&g_deg[d.x], 1);
        atomicAdd(&g_deg[d.y], 1);
        atomicAdd(&g_deg[d.z], 1);
        atomicAdd(&g_deg[d.w], 1);
    }
}
__global__ void k_dinv() {
    int v = blockIdx.x * 256 + threadIdx.x;
    if (v < NN) g_dinv[v] = rsqrtf((float)g_deg[v]);
}

// ================= SIDE-STREAM CSR chain (structure only) =================
__global__ void k_zero() {
    int v = blockIdx.x * 256 + threadIdx.x;
    if (v < NN) g_cnt[v] = 0;
}
__global__ void k_hist4(const int* __restrict__ dst) {
    int t = blockIdx.x * 256 + threadIdx.x;
    if (t < NE / 4) {
        int4 d = ((const int4*)dst)[t];
        atomicAdd(&g_cnt[d.x], 1);
        atomicAdd(&g_cnt[d.y], 1);
        atomicAdd(&g_cnt[d.z], 1);
        atomicAdd(&g_cnt[d.w], 1);
    }
}
__global__ __launch_bounds__(1024) void k_scan() {
    __shared__ int sums[1024];
    const int tid = threadIdx.x;
    const int CH = (NN + 1023) / 1024;
    const int start = tid * CH;
    const int end = min(start + CH, NN);
    int s = 0;
    for (int i = start; i < end; i++) s += g_cnt[i];
    sums[tid] = s;
    __syncthreads();
    for (int off = 1; off < 1024; off <<= 1) {
        int v = (tid >= off) ? sums[tid - off] : 0;
        __syncthreads();
        sums[tid] += v;
        __syncthreads();
    }
    int run = (tid == 0) ? 0 : sums[tid - 1];
    for (int i = start; i < end; i++) {
        int c = g_cnt[i];
        g_base[i] = run;
        g_cur[i] = run;
        run += c;
    }
}
__global__ void k_build4(const int* __restrict__ src, const int* __restrict__ dst) {
    int t = blockIdx.x * 256 + threadIdx.x;
    if (t < NE / 4) {
        int4 s = ((const int4*)src)[t];
        int4 d = ((const int4*)dst)[t];
        int p0 = atomicAdd(&g_cur[d.x], 1);
        int p1 = atomicAdd(&g_cur[d.y], 1);
        int p2 = atomicAdd(&g_cur[d.z], 1);
        int p3 = atomicAdd(&g_cur[d.w], 1);
        g_eidx[p0] = s.x;
        g_eidx[p1] = s.y;
        g_eidx[p2] = s.z;
        g_eidx[p3] = s.w;
    }
}

// ---------------- W1 prep: transpose + bf16 hi/lo split (main stream) ----------------
__global__ void k_prepW(const float* __restrict__ W1) {
    int idx = blockIdx.x * 256 + threadIdx.x;
    if (idx >= NF * NH) return;
    int k = idx >> 7;
    int n = idx & 127;
    float v = W1[idx];                 // W1[k][n]
    __nv_bfloat16 h = __float2bfloat16(v);
    g_W1h[n * NF + k] = h;
    g_W1l[n * NF + k] = __float2bfloat16(v - __bfloat162float(h));
}

// ---------------- GEMM1 (mma.sync bf16, 3-term split, reg double-buffer) ----------------
#define SSTR 20
__global__ __launch_bounds__(256) void k_gemm1_mma(const float* __restrict__ x) {
    __shared__ uint32_t uAh[128 * SSTR], uAl[128 * SSTR];
    __shared__ uint32_t uBh[128 * SSTR], uBl[128 * SSTR];

    const int tid = threadIdx.x;
    const int w = tid >> 5;
    const int lane = tid & 31;
    const int g = lane >> 2;
    const int tig = lane & 3;
    const int row0 = blockIdx.x * 128;

    // staging coordinates (fixed per thread)
    const int s_ar = tid >> 3;                 // A row for q-th: idx=tid+q*256 -> ar=idx>>3
    const int s_aq = tid & 7;
    float4 pa[4];
    uint4 pb[4];

    float acc[16][4];
#pragma unroll
    for (int nt = 0; nt < 16; nt++)
#pragma unroll
        for (int i = 0; i < 4; i++) acc[nt][i] = 0.f;

    // prefetch chunk 0
#pragma unroll
    for (int q = 0; q < 4; q++) {
        int idx = tid + q * 256;
        int ar = idx >> 3, aq = idx & 7;
        int gr = min(row0 + ar, NN - 1);
        pa[q] = *(const float4*)&x[(size_t)gr * NF + 0 + aq * 4];
        int mat = idx >> 9, br = (idx >> 2) & 127, bc = idx & 3;
        const __nv_bfloat16* gsrc = mat ? g_W1l : g_W1h;
        pb[q] = *(const uint4*)&gsrc[(size_t)br * NF + 0 + bc * 8];
    }

    for (int ch = 0; ch < 8; ch++) {
        __syncthreads();   // previous compute done reading smem
        // convert + STS from prefetch regs
#pragma unroll
        for (int q = 0; q < 4; q++) {
            int idx = tid + q * 256;
            int ar = idx >> 3, aq = idx & 7;
            float4 v = pa[q];
            __nv_bfloat16 hx = __float2bfloat16(v.x), hy = __float2bfloat16(v.y);
            __nv_bfloat16 hz = __float2bfloat16(v.z), hw = __float2bfloat16(v.w);
            uint32_t* ph = &uAh[ar * SSTR + aq * 2];
            uint32_t* pl = &uAl[ar * SSTR + aq * 2];
            ph[0] = pkbf(hx, hy);
            ph[1] = pkbf(hz, hw);
            pl[0] = pkbf(__float2bfloat16(v.x - __bfloat162float(hx)),
                         __float2bfloat16(v.y - __bfloat162float(hy)));
            pl[1] = pkbf(__float2bfloat16(v.z - __bfloat162float(hz)),
                         __float2bfloat16(v.w - __bfloat162float(hw)));
            int mat = idx >> 9, br = (idx >> 2) & 127, bc = idx & 3;
            uint32_t* p = (mat ? uBl : uBh) + br * SSTR + bc * 4;
            p[0] = pb[q].x; p[1] = pb[q].y; p[2] = pb[q].z; p[3] = pb[q].w;
        }
        __syncthreads();
        // prefetch next chunk (LDG latency hidden behind compute below)
        if (ch < 7) {
            const int kn = (ch + 1) * 32;
#pragma unroll
            for (int q = 0; q < 4; q++) {
                int idx = tid + q * 256;
                int ar = idx >> 3, aq = idx & 7;
                int gr = min(row0 + ar, NN - 1);
                pa[q] = *(const float4*)&x[(size_t)gr * NF + kn + aq * 4];
                int mat = idx >> 9, br = (idx >> 2) & 127, bc = idx & 3;
                const __nv_bfloat16* gsrc = mat ? g_W1l : g_W1h;
                pb[q] = *(const uint4*)&gsrc[(size_t)br * NF + kn + bc * 8];
            }
        }
        // compute current chunk
#pragma unroll
        for (int ks = 0; ks < 2; ks++) {
            const int ko = ks * 8;
            const int ra0 = (w * 16 + g) * SSTR + tig + ko;
            const int ra1 = (w * 16 + g + 8) * SSTR + tig + ko;
            uint32_t ah0 = uAh[ra0],     ah1 = uAh[ra1];
            uint32_t ah2 = uAh[ra0 + 4], ah3 = uAh[ra1 + 4];
            uint32_t al0 = uAl[ra0],     al1 = uAl[ra1];
            uint32_t al2 = uAl[ra0 + 4], al3 = uAl[ra1 + 4];
#pragma unroll
            for (int nt = 0; nt < 16; nt++) {
                const int rb = (nt * 8 + g) * SSTR + tig + ko;
                uint32_t bh0 = uBh[rb], bh1 = uBh[rb + 4];
                uint32_t bl0 = uBl[rb], bl1 = uBl[rb + 4];
                hmma16816(acc[nt], ah0, ah1, ah2, ah3, bh0, bh1);
                hmma16816(acc[nt], ah0, ah1, ah2, ah3, bl0, bl1);
                hmma16816(acc[nt], al0, al1, al2, al3, bh0, bh1);
            }
        }
    }
    // epilogue: scale by dinv (produced on THIS stream) and store
    const int r0 = row0 + w * 16 + g;
    const int r1 = r0 + 8;
    const float dv0 = (r0 < NN) ? g_dinv[r0] : 0.f;
    const float dv1 = (r1 < NN) ? g_dinv[r1] : 0.f;
#pragma unroll
    for (int nt = 0; nt < 16; nt++) {
        const int col = nt * 8 + tig * 2;
        if (r0 < NN) {
            float2 o0 = {acc[nt][0] * dv0, acc[nt][1] * dv0};
            *(float2*)&g_G1[(size_t)r0 * NH + col] = o0;
        }
        if (r1 < NN) {
            float2 o1 = {acc[nt][2] * dv1, acc[nt][3] * dv1};
            *(float2*)&g_G1[(size_t)r1 * NH + col] = o1;
        }
    }
}

// ---------------- agg layer1 (CSR gather, unroll 8) + bias/relu/mask fused ----------------
__global__ __launch_bounds__(128) void k_agg1(const float* __restrict__ b1,
                                              const float* __restrict__ mask) {
    const int v = blockIdx.x;
    const int tid = threadIdx.x;
    float a0 = g_G1[(size_t)v * NH + tid];
    float a1 = 0.f, a2 = 0.f, a3 = 0.f;
    float a4 = 0.f, a5 = 0.f, a6 = 0.f, a7 = 0.f;
    const int beg = g_base[v];
    const int n = g_cnt[v];
    int j = 0;
    for (; j + 8 <= n; j += 8) {
        int s0 = g_eidx[beg + j];
        int s1 = g_eidx[beg + j + 1];
        int s2 = g_eidx[beg + j + 2];
        int s3 = g_eidx[beg + j + 3];
        int s4 = g_eidx[beg + j + 4];
        int s5 = g_eidx[beg + j + 5];
        int s6 = g_eidx[beg + j + 6];
        int s7 = g_eidx[beg + j + 7];
        a0 += g_G1[(size_t)s0 * NH + tid];
        a1 += g_G1[(size_t)s1 * NH + tid];
        a2 += g_G1[(size_t)s2 * NH + tid];
        a3 += g_G1[(size_t)s3 * NH + tid];
        a4 += g_G1[(size_t)s4 * NH + tid];
        a5 += g_G1[(size_t)s5 * NH + tid];
        a6 += g_G1[(size_t)s6 * NH + tid];
        a7 += g_G1[(size_t)s7 * NH + tid];
    }
    for (; j + 4 <= n; j += 4) {
        int s0 = g_eidx[beg + j];
        int s1 = g_eidx[beg + j + 1];
        int s2 = g_eidx[beg + j + 2];
        int s3 = g_eidx[beg + j + 3];
        a0 += g_G1[(size_t)s0 * NH + tid];
        a1 += g_G1[(size_t)s1 * NH + tid];
        a2 += g_G1[(size_t)s2 * NH + tid];
        a3 += g_G1[(size_t)s3 * NH + tid];
    }
    for (; j < n; j++) a0 += g_G1[(size_t)g_eidx[beg + j] * NH + tid];
    float acc = ((a0 + a1) + (a2 + a3)) + ((a4 + a5) + (a6 + a7));
    float h = fmaxf(fmaf(acc, g_dinv[v], b1[tid]), 0.f) * mask[(size_t)v * NH + tid];
    g_H1[(size_t)v * NH + tid] = h;
}

// ---------------- GEMM2: G2 = dinv * (H1 @ W2) ----------------
__global__ __launch_bounds__(320) void k_gemm2(const float* __restrict__ W2) {
    __shared__ float ws[NH * NC];
    const int tid = threadIdx.x;
    for (int i = tid; i < NH * NC; i += 320) ws[i] = W2[i];
    __syncthreads();

    const int cg = tid % 10;
    const int rg = tid / 10;
    const int row0 = blockIdx.x * 128;

    float acc[4][4];
#pragma unroll
    for (int r = 0; r < 4; r++)
#pragma unroll
        for (int c = 0; c < 4; c++) acc[r][c] = 0.f;

    int grc[4];
#pragma unroll
    for (int r = 0; r < 4; r++) grc[r] = min(row0 + rg + 32 * r, NN - 1);

    for (int k0 = 0; k0 < NH; k0 += 4) {
        float4 hv[4];
#pragma unroll
        for (int r = 0; r < 4; r++)
            hv[r] = *(const float4*)&g_H1[(size_t)grc[r] * NH + k0];
#pragma unroll
        for (int kk = 0; kk < 4; kk++) {
            float4 wv = *(float4*)&ws[(k0 + kk) * NC + cg * 4];
#pragma unroll
            for (int r = 0; r < 4; r++) {
                float xv = (kk == 0) ? hv[r].x : (kk == 1) ? hv[r].y
                         : (kk == 2) ? hv[r].z : hv[r].w;
                acc[r][0] += xv * wv.x; acc[r][1] += xv * wv.y;
                acc[r][2] += xv * wv.z; acc[r][3] += xv * wv.w;
            }
        }
    }
#pragma unroll
    for (int r = 0; r < 4; r++) {
        int gr = row0 + rg + 32 * r;
        if (gr < NN) {
            float dv = g_dinv[gr];
            float4 o;
            o.x = acc[r][0] * dv; o.y = acc[r][1] * dv;
            o.z = acc[r][2] * dv; o.w = acc[r][3] * dv;
            *(float4*)&g_G2[(size_t)gr * NC + cg * 4] = o;
        }
    }
}

// ---------------- agg layer2 (CSR gather) + bias + log_softmax fused ----------------
__global__ __launch_bounds__(256) void k_agg2(const float* __restrict__ b2,
                                              float* __restrict__ out) {
    const int w = (blockIdx.x * blockDim.x + threadIdx.x) >> 5;
    const int lane = threadIdx.x & 31;
    if (w >= NN) return;
    const size_t rb = (size_t)w * NC;
    const bool hi = (lane < NC - 32);

    float a0 = g_G2[rb + lane];
    float a1 = hi ? g_G2[rb + 32 + lane] : 0.f;
    float c0 = 0.f, c1 = 0.f;
    const int beg = g_base[w];
    const int n = g_cnt[w];
    int j = 0;
    for (; j + 2 <= n; j += 2) {
        size_t sb0 = (size_t)g_eidx[beg + j] * NC;
        size_t sb1 = (size_t)g_eidx[beg + j + 1] * NC;
        a0 += g_G2[sb0 + lane];
        c0 += g_G2[sb1 + lane];
        if (hi) { a1 += g_G2[sb0 + 32 + lane]; c1 += g_G2[sb1 + 32 + lane]; }
    }
    if (j < n) {
        size_t sb = (size_t)g_eidx[beg + j] * NC;
        a0 += g_G2[sb + lane];
        if (hi) a1 += g_G2[sb + 32 + lane];
    }
    a0 += c0; a1 += c1;

    const float dv = g_dinv[w];
    float v0 = fmaf(a0, dv, b2[lane]);
    float v1 = hi ? fmaf(a1, dv, b2[32 + lane]) : -1e30f;

    float m = fmaxf(v0, v1);
#pragma unroll
    for (int o = 16; o; o >>= 1) m = fmaxf(m, __shfl_xor_sync(0xFFFFFFFFu, m, o));
    float s = expf(v0 - m) + (hi ? expf(v1 - m) : 0.f);
#pragma unroll
    for (int o = 16; o; o >>= 1) s += __shfl_xor_sync(0xFFFFFFFFu, s, o);
    float l = m + logf(s);
    out[rb + lane] = v0 - l;
    if (hi) out[rb + 32 + lane] = v1 - l;
}

// ---------------- fork-join resources (created pre-baseline in static init) ----------------
static cudaStream_t g_s = 0;
static cudaEvent_t g_e0 = 0, g_e1 = 0;
static struct GcnInit {
    GcnInit() {
        if (cudaStreamCreateWithFlags(&g_s, cudaStreamNonBlocking) != cudaSuccess) { g_s = 0; return; }
        if (cudaEventCreateWithFlags(&g_e0, cudaEventDisableTiming) != cudaSuccess) { g_e0 = 0; return; }
        if (cudaEventCreateWithFlags(&g_e1, cudaEventDisableTiming) != cudaSuccess) { g_e1 = 0; }
    }
} g_gcn_init;

// ---------------- launch ----------------
extern "C" void kernel_launch(void* const* d_in, const int* in_sizes, int n_in,
                              void* d_out, int out_size) {
    const float* x    = (const float*)d_in[0];
    const int*   ei   = (const int*)d_in[1];
    const float* W1   = (const float*)d_in[2];
    const float* b1   = (const float*)d_in[3];
    const float* W2   = (const float*)d_in[4];
    const float* b2   = (const float*)d_in[5];
    const float* mask = (const float*)d_in[6];
    float*       out  = (float*)d_out;

    const int* src = ei;
    const int* dst = ei + NE;

    // Fork: side stream builds CSR structure only (cnt/base/cur/eidx).
    bool fork = (g_s != 0) && (g_e0 != 0) && (g_e1 != 0);
    if (fork) fork = (cudaEventRecord(g_e0, 0) == cudaSuccess);
    if (fork) fork = (cudaStreamWaitEvent(g_s, g_e0, 0) == cudaSuccess);
    cudaStream_t cs = fork ? g_s : 0;

    // SIDE: CSR structure
    k_zero   <<<(NN + 255) / 256, 256, 0, cs>>>();
    k_hist4  <<<(NE / 4 + 255) / 256, 256, 0, cs>>>(dst);
    k_scan   <<<1, 1024, 0, cs>>>();
    k_build4 <<<(NE / 4 + 255) / 256, 256, 0, cs>>>(src, dst);

    // MAIN: own dinv (duplicate histogram) -> prepW -> gemm1 (scaled epilogue)
    k_zerodeg <<<(NN + 255) / 256, 256>>>();
    k_histdeg <<<(NE / 4 + 255) / 256, 256>>>(dst);
    k_dinv    <<<(NN + 255) / 256, 256>>>();
    k_prepW     <<<(NF * NH + 255) / 256, 256>>>(W1);
    k_gemm1_mma <<<(NN + 127) / 128, 256>>>(x);

    // join: agg1 needs CSR structure from side stream
    if (fork) {
        cudaEventRecord(g_e1, g_s);
        cudaStreamWaitEvent(0, g_e1, 0);
    }

    k_agg1  <<<NN, 128>>>(b1, mask);
    k_gemm2 <<<(NN + 127) / 128, 320>>>(W2);
    k_agg2  <<<(NN * 32 + 255) / 256, 256>>>(b2, out);
}

// round 15
// speedup vs baseline: 1.1184x; 1.1184x over previous
#include <cuda_runtime.h>
#include <cuda_bf16.h>
#include <cuda_fp16.h>
#include <math.h>
#include <stdint.h>

#define NN 50000
#define NE 1600000
#define NF 256
#define NH 128
#define NC 40

// ---------------- scratch (no allocations allowed) ----------------
__device__ float g_dinv[NN];    // main-stream product
__device__ int   g_deg[NN];     // main-stream histogram (self-loop incl.)
__device__ int   g_cnt[NN];     // side-stream histogram
__device__ int   g_base[NN];
__device__ int   g_cur[NN];
__device__ int   g_eidx[NE];
__device__ __align__(16) __half g_G1h[(size_t)NN * NH];  // fp16: dinv * (X @ W1)
__device__ __align__(16) float  g_H1[(size_t)NN * NH];   // fp32: relu(...)*mask
__device__ __align__(16) __half g_G2h[(size_t)NN * NC];  // fp16: dinv * (H1 @ W2)
__device__ __align__(16) __nv_bfloat16 g_W1h[NF * NH];   // transposed: [n][k] = n*NF+k
__device__ __align__(16) __nv_bfloat16 g_W1l[NF * NH];

static __device__ __forceinline__ uint32_t pkbf(__nv_bfloat16 a, __nv_bfloat16 b) {
    uint16_t ua = *(uint16_t*)&a, ub = *(uint16_t*)&b;
    return (uint32_t)ua | ((uint32_t)ub << 16);
}

static __device__ __forceinline__ void hmma16816(float* c, uint32_t a0, uint32_t a1,
                                                 uint32_t a2, uint32_t a3,
                                                 uint32_t b0, uint32_t b1) {
    asm volatile("mma.sync.aligned.m16n8k16.row.col.f32.bf16.bf16.f32 "
                 "{%0,%1,%2,%3}, {%4,%5,%6,%7}, {%8,%9}, {%0,%1,%2,%3};"
                 : "+f"(c[0]), "+f"(c[1]), "+f"(c[2]), "+f"(c[3])
                 : "r"(a0), "r"(a1), "r"(a2), "r"(a3), "r"(b0), "r"(b1));
}

// ================= MAIN-STREAM degree/dinv chain =================
__global__ void k_zerodeg() {
    int v = blockIdx.x * 256 + threadIdx.x;
    if (v < NN) g_deg[v] = 1;            // self-loop
}
__global__ void k_histdeg(const int* __restrict__ dst) {
    int t = blockIdx.x * 256 + threadIdx.x;
    if (t < NE / 4) {
        int4 d = ((const int4*)dst)[t];
        atomicAdd(&g_deg[d.x], 1);
        atomicAdd(&g_deg[d.y], 1);
        atomicAdd(&g_deg[d.z], 1);
        atomicAdd(&g_deg[d.w], 1);
    }
}
__global__ void k_dinv() {
    int v = blockIdx.x * 256 + threadIdx.x;
    if (v < NN) g_dinv[v] = rsqrtf((float)g_deg[v]);
}

// ================= SIDE-STREAM CSR chain (structure only) =================
__global__ void k_zero() {
    int v = blockIdx.x * 256 + threadIdx.x;
    if (v < NN) g_cnt[v] = 0;
}
__global__ void k_hist4(const int* __restrict__ dst) {
    int t = blockIdx.x * 256 + threadIdx.x;
    if (t < NE / 4) {
        int4 d = ((const int4*)dst)[t];
        atomicAdd(&g_cnt[d.x], 1);
        atomicAdd(&g_cnt[d.y], 1);
        atomicAdd(&g_cnt[d.z], 1);
        atomicAdd(&g_cnt[d.w], 1);
    }
}
__global__ __launch_bounds__(1024) void k_scan() {
    __shared__ int sums[1024];
    const int tid = threadIdx.x;
    const int CH = (NN + 1023) / 1024;
    const int start = tid * CH;
    const int end = min(start + CH, NN);
    int s = 0;
    for (int i = start; i < end; i++) s += g_cnt[i];
    sums[tid] = s;
    __syncthreads();
    for (int off = 1; off < 1024; off <<= 1) {
        int v = (tid >= off) ? sums[tid - off] : 0;
        __syncthreads();
        sums[tid] += v;
        __syncthreads();
    }
    int run = (tid == 0) ? 0 : sums[tid - 1];
    for (int i = start; i < end; i++) {
        int c = g_cnt[i];
        g_base[i] = run;
        g_cur[i] = run;
        run += c;
    }
}
__global__ void k_build4(const int* __restrict__ src, const int* __restrict__ dst) {
    int t = blockIdx.x * 256 + threadIdx.x;
    if (t < NE / 4) {
        int4 s = ((const int4*)src)[t];
        int4 d = ((const int4*)dst)[t];
        int p0 = atomicAdd(&g_cur[d.x], 1);
        int p1 = atomicAdd(&g_cur[d.y], 1);
        int p2 = atomicAdd(&g_cur[d.z], 1);
        int p3 = atomicAdd(&g_cur[d.w], 1);
        g_eidx[p0] = s.x;
        g_eidx[p1] = s.y;
        g_eidx[p2] = s.z;
        g_eidx[p3] = s.w;
    }
}

// ---------------- W1 prep: transpose + bf16 hi/lo split (main stream) ----------------
__global__ void k_prepW(const float* __restrict__ W1) {
    int idx = blockIdx.x * 256 + threadIdx.x;
    if (idx >= NF * NH) return;
    int k = idx >> 7;
    int n = idx & 127;
    float v = W1[idx];                 // W1[k][n]
    __nv_bfloat16 h = __float2bfloat16(v);
    g_W1h[n * NF + k] = h;
    g_W1l[n * NF + k] = __float2bfloat16(v - __bfloat162float(h));
}

// ---------------- GEMM1 (mma.sync bf16, 3-term split, reg double-buffer) ----------------
#define SSTR 20
__global__ __launch_bounds__(256) void k_gemm1_mma(const float* __restrict__ x) {
    __shared__ uint32_t uAh[128 * SSTR], uAl[128 * SSTR];
    __shared__ uint32_t uBh[128 * SSTR], uBl[128 * SSTR];

    const int tid = threadIdx.x;
    const int w = tid >> 5;
    const int lane = tid & 31;
    const int g = lane >> 2;
    const int tig = lane & 3;
    const int row0 = blockIdx.x * 128;

    float4 pa[4];
    uint4 pb[4];

    float acc[16][4];
#pragma unroll
    for (int nt = 0; nt < 16; nt++)
#pragma unroll
        for (int i = 0; i < 4; i++) acc[nt][i] = 0.f;

    // prefetch chunk 0
#pragma unroll
    for (int q = 0; q < 4; q++) {
        int idx = tid + q * 256;
        int ar = idx >> 3, aq = idx & 7;
        int gr = min(row0 + ar, NN - 1);
        pa[q] = *(const float4*)&x[(size_t)gr * NF + 0 + aq * 4];
        int mat = idx >> 9, br = (idx >> 2) & 127, bc = idx & 3;
        const __nv_bfloat16* gsrc = mat ? g_W1l : g_W1h;
        pb[q] = *(const uint4*)&gsrc[(size_t)br * NF + 0 + bc * 8];
    }

    for (int ch = 0; ch < 8; ch++) {
        __syncthreads();
#pragma unroll
        for (int q = 0; q < 4; q++) {
            int idx = tid + q * 256;
            int ar = idx >> 3, aq = idx & 7;
            float4 v = pa[q];
            __nv_bfloat16 hx = __float2bfloat16(v.x), hy = __float2bfloat16(v.y);
            __nv_bfloat16 hz = __float2bfloat16(v.z), hw = __float2bfloat16(v.w);
            uint32_t* ph = &uAh[ar * SSTR + aq * 2];
            uint32_t* pl = &uAl[ar * SSTR + aq * 2];
            ph[0] = pkbf(hx, hy);
            ph[1] = pkbf(hz, hw);
            pl[0] = pkbf(__float2bfloat16(v.x - __bfloat162float(hx)),
                         __float2bfloat16(v.y - __bfloat162float(hy)));
            pl[1] = pkbf(__float2bfloat16(v.z - __bfloat162float(hz)),
                         __float2bfloat16(v.w - __bfloat162float(hw)));
            int mat = idx >> 9, br = (idx >> 2) & 127, bc = idx & 3;
            uint32_t* p = (mat ? uBl : uBh) + br * SSTR + bc * 4;
            p[0] = pb[q].x; p[1] = pb[q].y; p[2] = pb[q].z; p[3] = pb[q].w;
        }
        __syncthreads();
        if (ch < 7) {
            const int kn = (ch + 1) * 32;
#pragma unroll
            for (int q = 0; q < 4; q++) {
                int idx = tid + q * 256;
                int ar = idx >> 3, aq = idx & 7;
                int gr = min(row0 + ar, NN - 1);
                pa[q] = *(const float4*)&x[(size_t)gr * NF + kn + aq * 4];
                int mat = idx >> 9, br = (idx >> 2) & 127, bc = idx & 3;
                const __nv_bfloat16* gsrc = mat ? g_W1l : g_W1h;
                pb[q] = *(const uint4*)&gsrc[(size_t)br * NF + kn + bc * 8];
            }
        }
#pragma unroll
        for (int ks = 0; ks < 2; ks++) {
            const int ko = ks * 8;
            const int ra0 = (w * 16 + g) * SSTR + tig + ko;
            const int ra1 = (w * 16 + g + 8) * SSTR + tig + ko;
            uint32_t ah0 = uAh[ra0],     ah1 = uAh[ra1];
            uint32_t ah2 = uAh[ra0 + 4], ah3 = uAh[ra1 + 4];
            uint32_t al0 = uAl[ra0],     al1 = uAl[ra1];
            uint32_t al2 = uAl[ra0 + 4], al3 = uAl[ra1 + 4];
#pragma unroll
            for (int nt = 0; nt < 16; nt++) {
                const int rb = (nt * 8 + g) * SSTR + tig + ko;
                uint32_t bh0 = uBh[rb], bh1 = uBh[rb + 4];
                uint32_t bl0 = uBl[rb], bl1 = uBl[rb + 4];
                hmma16816(acc[nt], ah0, ah1, ah2, ah3, bh0, bh1);
                hmma16816(acc[nt], ah0, ah1, ah2, ah3, bl0, bl1);
                hmma16816(acc[nt], al0, al1, al2, al3, bh0, bh1);
            }
        }
    }
    // epilogue: scale by dinv, convert to fp16, store
    const int r0 = row0 + w * 16 + g;
    const int r1 = r0 + 8;
    const float dv0 = (r0 < NN) ? g_dinv[r0] : 0.f;
    const float dv1 = (r1 < NN) ? g_dinv[r1] : 0.f;
#pragma unroll
    for (int nt = 0; nt < 16; nt++) {
        const int col = nt * 8 + tig * 2;
        if (r0 < NN)
            *(__half2*)&g_G1h[(size_t)r0 * NH + col] =
                __floats2half2_rn(acc[nt][0] * dv0, acc[nt][1] * dv0);
        if (r1 < NN)
            *(__half2*)&g_G1h[(size_t)r1 * NH + col] =
                __floats2half2_rn(acc[nt][2] * dv1, acc[nt][3] * dv1);
    }
}

// ---------------- agg layer1: fp16 gather, fp32 accumulate ----------------
// 64 threads per node; thread = half2 column pair
__global__ __launch_bounds__(64) void k_agg1(const float* __restrict__ b1,
                                             const float* __restrict__ mask) {
    const int v = blockIdx.x;
    const int tid = threadIdx.x;     // 0..63
    const __half2* G1 = (const __half2*)g_G1h;  // row stride 64
    float2 s0 = __half22float2(G1[(size_t)v * 64 + tid]);  // self-loop
    float ax0 = s0.x, ay0 = s0.y;
    float ax1 = 0.f, ay1 = 0.f, ax2 = 0.f, ay2 = 0.f, ax3 = 0.f, ay3 = 0.f;
    const int beg = g_base[v];
    const int n = g_cnt[v];
    int j = 0;
    for (; j + 4 <= n; j += 4) {
        int e0 = g_eidx[beg + j];
        int e1 = g_eidx[beg + j + 1];
        int e2 = g_eidx[beg + j + 2];
        int e3 = g_eidx[beg + j + 3];
        float2 f0 = __half22float2(G1[(size_t)e0 * 64 + tid]);
        float2 f1 = __half22float2(G1[(size_t)e1 * 64 + tid]);
        float2 f2 = __half22float2(G1[(size_t)e2 * 64 + tid]);
        float2 f3 = __half22float2(G1[(size_t)e3 * 64 + tid]);
        ax0 += f0.x; ay0 += f0.y;
        ax1 += f1.x; ay1 += f1.y;
        ax2 += f2.x; ay2 += f2.y;
        ax3 += f3.x; ay3 += f3.y;
    }
    for (; j < n; j++) {
        int e = g_eidx[beg + j];
        float2 f = __half22float2(G1[(size_t)e * 64 + tid]);
        ax0 += f.x; ay0 += f.y;
    }
    float accx = (ax0 + ax1) + (ax2 + ax3);
    float accy = (ay0 + ay1) + (ay2 + ay3);
    const float dv = g_dinv[v];
    float2 bb = *(const float2*)&b1[2 * tid];
    float2 mm = *(const float2*)&mask[(size_t)v * NH + 2 * tid];
    float2 h;
    h.x = fmaxf(fmaf(accx, dv, bb.x), 0.f) * mm.x;
    h.y = fmaxf(fmaf(accy, dv, bb.y), 0.f) * mm.y;
    *(float2*)&g_H1[(size_t)v * NH + 2 * tid] = h;
}

// ---------------- GEMM2: G2 = dinv * (H1 @ W2), fp16 output ----------------
__global__ __launch_bounds__(320) void k_gemm2(const float* __restrict__ W2) {
    __shared__ float ws[NH * NC];
    const int tid = threadIdx.x;
    for (int i = tid; i < NH * NC; i += 320) ws[i] = W2[i];
    __syncthreads();

    const int cg = tid % 10;
    const int rg = tid / 10;
    const int row0 = blockIdx.x * 128;

    float acc[4][4];
#pragma unroll
    for (int r = 0; r < 4; r++)
#pragma unroll
        for (int c = 0; c < 4; c++) acc[r][c] = 0.f;

    int grc[4];
#pragma unroll
    for (int r = 0; r < 4; r++) grc[r] = min(row0 + rg + 32 * r, NN - 1);

    for (int k0 = 0; k0 < NH; k0 += 4) {
        float4 hv[4];
#pragma unroll
        for (int r = 0; r < 4; r++)
            hv[r] = *(const float4*)&g_H1[(size_t)grc[r] * NH + k0];
#pragma unroll
        for (int kk = 0; kk < 4; kk++) {
            float4 wv = *(float4*)&ws[(k0 + kk) * NC + cg * 4];
#pragma unroll
            for (int r = 0; r < 4; r++) {
                float xv = (kk == 0) ? hv[r].x : (kk == 1) ? hv[r].y
                         : (kk == 2) ? hv[r].z : hv[r].w;
                acc[r][0] += xv * wv.x; acc[r][1] += xv * wv.y;
                acc[r][2] += xv * wv.z; acc[r][3] += xv * wv.w;
            }
        }
    }
#pragma unroll
    for (int r = 0; r < 4; r++) {
        int gr = row0 + rg + 32 * r;
        if (gr < NN) {
            float dv = g_dinv[gr];
            size_t off = (size_t)gr * NC + cg * 4;
            *(__half2*)&g_G2h[off]     = __floats2half2_rn(acc[r][0] * dv, acc[r][1] * dv);
            *(__half2*)&g_G2h[off + 2] = __floats2half2_rn(acc[r][2] * dv, acc[r][3] * dv);
        }
    }
}

// ---------------- agg layer2: fp16 gather + bias + log_softmax fused ----------------
// warp per node; lanes 0..19 each own class pair (2*lane, 2*lane+1)
__global__ __launch_bounds__(256) void k_agg2(const float* __restrict__ b2,
                                              float* __restrict__ out) {
    const int w = (blockIdx.x * blockDim.x + threadIdx.x) >> 5;
    const int lane = threadIdx.x & 31;
    if (w >= NN) return;
    const bool act = (lane < NC / 2);     // 20 active lanes
    const __half2* G2 = (const __half2*)g_G2h;  // row stride 20

    float ax = 0.f, ay = 0.f, cx = 0.f, cy = 0.f;
    if (act) {
        float2 f = __half22float2(G2[(size_t)w * 20 + lane]);  // self-loop
        ax = f.x; ay = f.y;
    }
    const int beg = g_base[w];
    const int n = g_cnt[w];
    int j = 0;
    for (; j + 2 <= n; j += 2) {
        int e0 = g_eidx[beg + j];
        int e1 = g_eidx[beg + j + 1];
        if (act) {
            float2 f0 = __half22float2(G2[(size_t)e0 * 20 + lane]);
            float2 f1 = __half22float2(G2[(size_t)e1 * 20 + lane]);
            ax += f0.x; ay += f0.y;
            cx += f1.x; cy += f1.y;
        }
    }
    if (j < n) {
        int e = g_eidx[beg + j];
        if (act) {
            float2 f = __half22float2(G2[(size_t)e * 20 + lane]);
            ax += f.x; ay += f.y;
        }
    }
    ax += cx; ay += cy;

    const float dv = g_dinv[w];
    float v0 = act ? fmaf(ax, dv, b2[2 * lane]) : -1e30f;
    float v1 = act ? fmaf(ay, dv, b2[2 * lane + 1]) : -1e30f;

    float m = fmaxf(v0, v1);
#pragma unroll
    for (int o = 16; o; o >>= 1) m = fmaxf(m, __shfl_xor_sync(0xFFFFFFFFu, m, o));
    float s = act ? (expf(v0 - m) + expf(v1 - m)) : 0.f;
#pragma unroll
    for (int o = 16; o; o >>= 1) s += __shfl_xor_sync(0xFFFFFFFFu, s, o);
    float l = m + logf(s);
    if (act) {
        const size_t rb = (size_t)w * NC;
        out[rb + 2 * lane] = v0 - l;
        out[rb + 2 * lane + 1] = v1 - l;
    }
}

// ---------------- fork-join resources (created pre-baseline in static init) ----------------
static cudaStream_t g_s = 0;
static cudaEvent_t g_e0 = 0, g_e1 = 0;
static struct GcnInit {
    GcnInit() {
        if (cudaStreamCreateWithFlags(&g_s, cudaStreamNonBlocking) != cudaSuccess) { g_s = 0; return; }
        if (cudaEventCreateWithFlags(&g_e0, cudaEventDisableTiming) != cudaSuccess) { g_e0 = 0; return; }
        if (cudaEventCreateWithFlags(&g_e1, cudaEventDisableTiming) != cudaSuccess) { g_e1 = 0; }
    }
} g_gcn_init;

// ---------------- launch ----------------
extern "C" void kernel_launch(void* const* d_in, const int* in_sizes, int n_in,
                              void* d_out, int out_size) {
    const float* x    = (const float*)d_in[0];
    const int*   ei   = (const int*)d_in[1];
    const float* W1   = (const float*)d_in[2];
    const float* b1   = (const float*)d_in[3];
    const float* W2   = (const float*)d_in[4];
    const float* b2   = (const float*)d_in[5];
    const float* mask = (const float*)d_in[6];
    float*       out  = (float*)d_out;

    const int* src = ei;
    const int* dst = ei + NE;

    // Fork: side stream builds CSR structure only (cnt/base/cur/eidx).
    bool fork = (g_s != 0) && (g_e0 != 0) && (g_e1 != 0);
    if (fork) fork = (cudaEventRecord(g_e0, 0) == cudaSuccess);
    if (fork) fork = (cudaStreamWaitEvent(g_s, g_e0, 0) == cudaSuccess);
    cudaStream_t cs = fork ? g_s : 0;

    // SIDE: CSR structure
    k_zero   <<<(NN + 255) / 256, 256, 0, cs>>>();
    k_hist4  <<<(NE / 4 + 255) / 256, 256, 0, cs>>>(dst);
    k_scan   <<<1, 1024, 0, cs>>>();
    k_build4 <<<(NE / 4 + 255) / 256, 256, 0, cs>>>(src, dst);

    // MAIN: own dinv (duplicate histogram) -> prepW -> gemm1
    k_zerodeg <<<(NN + 255) / 256, 256>>>();
    k_histdeg <<<(NE / 4 + 255) / 256, 256>>>(dst);
    k_dinv    <<<(NN + 255) / 256, 256>>>();
    k_prepW     <<<(NF * NH + 255) / 256, 256>>>(W1);
    k_gemm1_mma <<<(NN + 127) / 128, 256>>>(x);

    // join: agg1 needs CSR structure from side stream
    if (fork) {
        cudaEventRecord(g_e1, g_s);
        cudaStreamWaitEvent(0, g_e1, 0);
    }

    k_agg1  <<<NN, 64>>>(b1, mask);
    k_gemm2 <<<(NN + 127) / 128, 320>>>(W2);
    k_agg2  <<<(NN * 32 + 255) / 256, 256>>>(b2, out);
}

// round 16
// speedup vs baseline: 1.2514x; 1.1189x over previous
#include <cuda_runtime.h>
#include <cuda_fp16.h>
#include <math.h>
#include <stdint.h>

#define NN 50000
#define NE 1600000
#define NF 256
#define NH 128
#define NC 40

// ---------------- scratch (no allocations allowed) ----------------
__device__ float g_dinv[NN];
__device__ int   g_cnt[NN];
__device__ int   g_base[NN];
__device__ int   g_cur[NN];
__device__ int   g_eidx[NE];
__device__ __align__(16) __half g_G1h[(size_t)NN * NH];  // fp16: dinv * (X @ W1)
__device__ __align__(16) __half g_H1h[(size_t)NN * NH];  // fp16: relu(...)*mask
__device__ __align__(16) __half g_G2h[(size_t)NN * NC];  // fp16: dinv * (H1 @ W2)
__device__ __align__(16) __half g_W1f[NF * NH];          // fp16 W1 transposed: [n][k]
__device__ __align__(16) __half g_W2t[NH * NC];          // fp16 W2 transposed: [n][k] = n*128+k

static __device__ __forceinline__ void hmma16816_f16(float* c, uint32_t a0, uint32_t a1,
                                                     uint32_t a2, uint32_t a3,
                                                     uint32_t b0, uint32_t b1) {
    asm volatile("mma.sync.aligned.m16n8k16.row.col.f32.f16.f16.f32 "
                 "{%0,%1,%2,%3}, {%4,%5,%6,%7}, {%8,%9}, {%0,%1,%2,%3};"
                 : "+f"(c[0]), "+f"(c[1]), "+f"(c[2]), "+f"(c[3])
                 : "r"(a0), "r"(a1), "r"(a2), "r"(a3), "r"(b0), "r"(b1));
}
static __device__ __forceinline__ uint32_t pkh2(float a, float b) {
    __half2 h = __floats2half2_rn(a, b);
    return *(uint32_t*)&h;
}

// ================= SIDE-STREAM: CSR + dinv =================
__global__ void k_zero() {
    int v = blockIdx.x * 256 + threadIdx.x;
    if (v < NN) g_cnt[v] = 0;
}
__global__ void k_hist4(const int* __restrict__ dst) {
    int t = blockIdx.x * 256 + threadIdx.x;
    if (t < NE / 4) {
        int4 d = ((const int4*)dst)[t];
        atomicAdd(&g_cnt[d.x], 1);
        atomicAdd(&g_cnt[d.y], 1);
        atomicAdd(&g_cnt[d.z], 1);
        atomicAdd(&g_cnt[d.w], 1);
    }
}
__global__ void k_dinvC() {   // dinv from shared histogram (+1 self-loop)
    int v = blockIdx.x * 256 + threadIdx.x;
    if (v < NN) g_dinv[v] = rsqrtf((float)(g_cnt[v] + 1));
}
__global__ __launch_bounds__(1024) void k_scan() {
    __shared__ int sums[1024];
    const int tid = threadIdx.x;
    const int CH = (NN + 1023) / 1024;
    const int start = tid * CH;
    const int end = min(start + CH, NN);
    int s = 0;
    for (int i = start; i < end; i++) s += g_cnt[i];
    sums[tid] = s;
    __syncthreads();
    for (int off = 1; off < 1024; off <<= 1) {
        int v = (tid >= off) ? sums[tid - off] : 0;
        __syncthreads();
        sums[tid] += v;
        __syncthreads();
    }
    int run = (tid == 0) ? 0 : sums[tid - 1];
    for (int i = start; i < end; i++) {
        int c = g_cnt[i];
        g_base[i] = run;
        g_cur[i] = run;
        run += c;
    }
}
__global__ void k_build4(const int* __restrict__ src, const int* __restrict__ dst) {
    int t = blockIdx.x * 256 + threadIdx.x;
    if (t < NE / 4) {
        int4 s = ((const int4*)src)[t];
        int4 d = ((const int4*)dst)[t];
        int p0 = atomicAdd(&g_cur[d.x], 1);
        int p1 = atomicAdd(&g_cur[d.y], 1);
        int p2 = atomicAdd(&g_cur[d.z], 1);
        int p3 = atomicAdd(&g_cur[d.w], 1);
        g_eidx[p0] = s.x;
        g_eidx[p1] = s.y;
        g_eidx[p2] = s.z;
        g_eidx[p3] = s.w;
    }
}

// ---------------- weight prep (main stream) ----------------
__global__ void k_prepW(const float* __restrict__ W1) {
    int idx = blockIdx.x * 256 + threadIdx.x;
    if (idx >= NF * NH) return;
    int k = idx >> 7;
    int n = idx & 127;
    g_W1f[n * NF + k] = __float2half(W1[idx]);   // W1[k][n] -> [n][k]
}
__global__ void k_prepW2(const float* __restrict__ W2) {
    int idx = blockIdx.x * 256 + threadIdx.x;
    if (idx >= NH * NC) return;
    int k = idx / NC;
    int n = idx - k * NC;
    g_W2t[n * NH + k] = __float2half(W2[idx]);   // W2[k][n] -> [n][k]
}

// ---------------- GEMM1 (single-term fp16 mma): G1 = dinv * (X @ W1) ----------------
#define SSTR 20
__global__ __launch_bounds__(256) void k_gemm1_mma(const float* __restrict__ x) {
    __shared__ uint32_t uA[128 * SSTR];   // 128 rows x 16 words (32 halfs), pad 4
    __shared__ uint32_t uB[128 * SSTR];

    const int tid = threadIdx.x;
    const int w = tid >> 5;
    const int lane = tid & 31;
    const int g = lane >> 2;
    const int tig = lane & 3;
    const int row0 = blockIdx.x * 128;

    float4 pa[4];
    uint4 pb[2];

    float acc[16][4];
#pragma unroll
    for (int nt = 0; nt < 16; nt++)
#pragma unroll
        for (int i = 0; i < 4; i++) acc[nt][i] = 0.f;

    // prefetch chunk 0
#pragma unroll
    for (int q = 0; q < 4; q++) {
        int idx = tid + q * 256;
        int ar = idx >> 3, aq = idx & 7;
        int gr = min(row0 + ar, NN - 1);
        pa[q] = *(const float4*)&x[(size_t)gr * NF + 0 + aq * 4];
    }
#pragma unroll
    for (int q = 0; q < 2; q++) {
        int idx = tid + q * 256;           // 512 = 128 rows x 4 uint4
        int br = idx >> 2, bc = idx & 3;
        pb[q] = *(const uint4*)&g_W1f[(size_t)br * NF + 0 + bc * 8];
    }

    for (int ch = 0; ch < 8; ch++) {
        __syncthreads();
        // convert + STS
#pragma unroll
        for (int q = 0; q < 4; q++) {
            int idx = tid + q * 256;
            int ar = idx >> 3, aq = idx & 7;
            float4 v = pa[q];
            uint32_t* p = &uA[ar * SSTR + aq * 2];
            p[0] = pkh2(v.x, v.y);
            p[1] = pkh2(v.z, v.w);
        }
#pragma unroll
        for (int q = 0; q < 2; q++) {
            int idx = tid + q * 256;
            int br = idx >> 2, bc = idx & 3;
            uint32_t* p = &uB[br * SSTR + bc * 4];
            p[0] = pb[q].x; p[1] = pb[q].y; p[2] = pb[q].z; p[3] = pb[q].w;
        }
        __syncthreads();
        // prefetch next chunk
        if (ch < 7) {
            const int kn = (ch + 1) * 32;
#pragma unroll
            for (int q = 0; q < 4; q++) {
                int idx = tid + q * 256;
                int ar = idx >> 3, aq = idx & 7;
                int gr = min(row0 + ar, NN - 1);
                pa[q] = *(const float4*)&x[(size_t)gr * NF + kn + aq * 4];
            }
#pragma unroll
            for (int q = 0; q < 2; q++) {
                int idx = tid + q * 256;
                int br = idx >> 2, bc = idx & 3;
                pb[q] = *(const uint4*)&g_W1f[(size_t)br * NF + kn + bc * 8];
            }
        }
        // compute
#pragma unroll
        for (int ks = 0; ks < 2; ks++) {
            const int ko = ks * 8;
            const int ra0 = (w * 16 + g) * SSTR + tig + ko;
            const int ra1 = (w * 16 + g + 8) * SSTR + tig + ko;
            uint32_t a0 = uA[ra0],     a1 = uA[ra1];
            uint32_t a2 = uA[ra0 + 4], a3 = uA[ra1 + 4];
#pragma unroll
            for (int nt = 0; nt < 16; nt++) {
                const int rb = (nt * 8 + g) * SSTR + tig + ko;
                hmma16816_f16(acc[nt], a0, a1, a2, a3, uB[rb], uB[rb + 4]);
            }
        }
    }
    // epilogue: scale by dinv (side-stream product, event-ordered), store fp16
    const int r0 = row0 + w * 16 + g;
    const int r1 = r0 + 8;
    const float dv0 = (r0 < NN) ? g_dinv[r0] : 0.f;
    const float dv1 = (r1 < NN) ? g_dinv[r1] : 0.f;
#pragma unroll
    for (int nt = 0; nt < 16; nt++) {
        const int col = nt * 8 + tig * 2;
        if (r0 < NN)
            *(__half2*)&g_G1h[(size_t)r0 * NH + col] =
                __floats2half2_rn(acc[nt][0] * dv0, acc[nt][1] * dv0);
        if (r1 < NN)
            *(__half2*)&g_G1h[(size_t)r1 * NH + col] =
                __floats2half2_rn(acc[nt][2] * dv1, acc[nt][3] * dv1);
    }
}

// ---------------- agg layer1: fp16 gather, fp32 accumulate, fp16 H1 out ----------------
__global__ __launch_bounds__(64) void k_agg1(const float* __restrict__ b1,
                                             const float* __restrict__ mask) {
    const int v = blockIdx.x;
    const int tid = threadIdx.x;     // 0..63
    const __half2* G1 = (const __half2*)g_G1h;
    float2 s0 = __half22float2(G1[(size_t)v * 64 + tid]);
    float ax0 = s0.x, ay0 = s0.y;
    float ax1 = 0.f, ay1 = 0.f, ax2 = 0.f, ay2 = 0.f, ax3 = 0.f, ay3 = 0.f;
    const int beg = g_base[v];
    const int n = g_cnt[v];
    int j = 0;
    for (; j + 4 <= n; j += 4) {
        int e0 = g_eidx[beg + j];
        int e1 = g_eidx[beg + j + 1];
        int e2 = g_eidx[beg + j + 2];
        int e3 = g_eidx[beg + j + 3];
        float2 f0 = __half22float2(G1[(size_t)e0 * 64 + tid]);
        float2 f1 = __half22float2(G1[(size_t)e1 * 64 + tid]);
        float2 f2 = __half22float2(G1[(size_t)e2 * 64 + tid]);
        float2 f3 = __half22float2(G1[(size_t)e3 * 64 + tid]);
        ax0 += f0.x; ay0 += f0.y;
        ax1 += f1.x; ay1 += f1.y;
        ax2 += f2.x; ay2 += f2.y;
        ax3 += f3.x; ay3 += f3.y;
    }
    for (; j < n; j++) {
        int e = g_eidx[beg + j];
        float2 f = __half22float2(G1[(size_t)e * 64 + tid]);
        ax0 += f.x; ay0 += f.y;
    }
    float accx = (ax0 + ax1) + (ax2 + ax3);
    float accy = (ay0 + ay1) + (ay2 + ay3);
    const float dv = g_dinv[v];
    float2 bb = *(const float2*)&b1[2 * tid];
    float2 mm = *(const float2*)&mask[(size_t)v * NH + 2 * tid];
    float hx = fmaxf(fmaf(accx, dv, bb.x), 0.f) * mm.x;
    float hy = fmaxf(fmaf(accy, dv, bb.y), 0.f) * mm.y;
    ((__half2*)g_H1h)[(size_t)v * 64 + tid] = __floats2half2_rn(hx, hy);
}

// ---------------- GEMM2 (fp16 mma): G2 = dinv * (H1 @ W2), fp16 out ----------------
__global__ __launch_bounds__(256) void k_gemm2_mma() {
    __shared__ uint32_t uA[128 * SSTR];  // 128 rows x 16 words (32 halfs)
    __shared__ uint32_t uB[40 * SSTR];   // 40 n-rows x 16 words

    const int tid = threadIdx.x;
    const int w = tid >> 5;
    const int lane = tid & 31;
    const int g = lane >> 2;
    const int tig = lane & 3;
    const int row0 = blockIdx.x * 128;

    float acc[5][4];
#pragma unroll
    for (int nt = 0; nt < 5; nt++)
#pragma unroll
        for (int i = 0; i < 4; i++) acc[nt][i] = 0.f;

    for (int ch = 0; ch < 4; ch++) {
        const int k0 = ch * 32;              // halfs
        __syncthreads();
        // stage A: 128 rows x 4 uint4 = 512
#pragma unroll
        for (int q = 0; q < 2; q++) {
            int idx = tid + q * 256;
            int ar = idx >> 2, ac = idx & 3;
            int gr = min(row0 + ar, NN - 1);
            uint4 v = *(const uint4*)&g_H1h[(size_t)gr * NH + k0 + ac * 8];
            uint32_t* p = &uA[ar * SSTR + ac * 4];
            p[0] = v.x; p[1] = v.y; p[2] = v.z; p[3] = v.w;
        }
        // stage B: 40 rows x 4 uint4 = 160
        if (tid < 160) {
            int br = tid >> 2, bc = tid & 3;
            uint4 v = *(const uint4*)&g_W2t[(size_t)br * NH + k0 + bc * 8];
            uint32_t* p = &uB[br * SSTR + bc * 4];
            p[0] = v.x; p[1] = v.y; p[2] = v.z; p[3] = v.w;
        }
        __syncthreads();
#pragma unroll
        for (int ks = 0; ks < 2; ks++) {
            const int ko = ks * 8;
            const int ra0 = (w * 16 + g) * SSTR + tig + ko;
            const int ra1 = (w * 16 + g + 8) * SSTR + tig + ko;
            uint32_t a0 = uA[ra0],     a1 = uA[ra1];
            uint32_t a2 = uA[ra0 + 4], a3 = uA[ra1 + 4];
#pragma unroll
            for (int nt = 0; nt < 5; nt++) {
                const int rb = (nt * 8 + g) * SSTR + tig + ko;
                hmma16816_f16(acc[nt], a0, a1, a2, a3, uB[rb], uB[rb + 4]);
            }
        }
    }
    const int r0 = row0 + w * 16 + g;
    const int r1 = r0 + 8;
    const float dv0 = (r0 < NN) ? g_dinv[r0] : 0.f;
    const float dv1 = (r1 < NN) ? g_dinv[r1] : 0.f;
#pragma unroll
    for (int nt = 0; nt < 5; nt++) {
        const int col = nt * 8 + tig * 2;
        if (r0 < NN)
            *(__half2*)&g_G2h[(size_t)r0 * NC + col] =
                __floats2half2_rn(acc[nt][0] * dv0, acc[nt][1] * dv0);
        if (r1 < NN)
            *(__half2*)&g_G2h[(size_t)r1 * NC + col] =
                __floats2half2_rn(acc[nt][2] * dv1, acc[nt][3] * dv1);
    }
}

// ---------------- agg layer2: fp16 gather + bias + log_softmax fused ----------------
__global__ __launch_bounds__(256) void k_agg2(const float* __restrict__ b2,
                                              float* __restrict__ out) {
    const int w = (blockIdx.x * blockDim.x + threadIdx.x) >> 5;
    const int lane = threadIdx.x & 31;
    if (w >= NN) return;
    const bool act = (lane < NC / 2);
    const __half2* G2 = (const __half2*)g_G2h;

    float ax = 0.f, ay = 0.f, cx = 0.f, cy = 0.f;
    if (act) {
        float2 f = __half22float2(G2[(size_t)w * 20 + lane]);
        ax = f.x; ay = f.y;
    }
    const int beg = g_base[w];
    const int n = g_cnt[w];
    int j = 0;
    for (; j + 2 <= n; j += 2) {
        int e0 = g_eidx[beg + j];
        int e1 = g_eidx[beg + j + 1];
        if (act) {
            float2 f0 = __half22float2(G2[(size_t)e0 * 20 + lane]);
            float2 f1 = __half22float2(G2[(size_t)e1 * 20 + lane]);
            ax += f0.x; ay += f0.y;
            cx += f1.x; cy += f1.y;
        }
    }
    if (j < n) {
        int e = g_eidx[beg + j];
        if (act) {
            float2 f = __half22float2(G2[(size_t)e * 20 + lane]);
            ax += f.x; ay += f.y;
        }
    }
    ax += cx; ay += cy;

    const float dv = g_dinv[w];
    float v0 = act ? fmaf(ax, dv, b2[2 * lane]) : -1e30f;
    float v1 = act ? fmaf(ay, dv, b2[2 * lane + 1]) : -1e30f;

    float m = fmaxf(v0, v1);
#pragma unroll
    for (int o = 16; o; o >>= 1) m = fmaxf(m, __shfl_xor_sync(0xFFFFFFFFu, m, o));
    float s = act ? (expf(v0 - m) + expf(v1 - m)) : 0.f;
#pragma unroll
    for (int o = 16; o; o >>= 1) s += __shfl_xor_sync(0xFFFFFFFFu, s, o);
    float l = m + logf(s);
    if (act) {
        const size_t rb = (size_t)w * NC;
        out[rb + 2 * lane] = v0 - l;
        out[rb + 2 * lane + 1] = v1 - l;
    }
}

// ---------------- fork-join resources (created pre-baseline in static init) ----------------
static cudaStream_t g_s = 0;
static cudaEvent_t g_e0 = 0, g_e1 = 0, g_e2 = 0;
static struct GcnInit {
    GcnInit() {
        if (cudaStreamCreateWithFlags(&g_s, cudaStreamNonBlocking) != cudaSuccess) { g_s = 0; return; }
        if (cudaEventCreateWithFlags(&g_e0, cudaEventDisableTiming) != cudaSuccess) { g_e0 = 0; return; }
        if (cudaEventCreateWithFlags(&g_e1, cudaEventDisableTiming) != cudaSuccess) { g_e1 = 0; return; }
        if (cudaEventCreateWithFlags(&g_e2, cudaEventDisableTiming) != cudaSuccess) { g_e2 = 0; }
    }
} g_gcn_init;

// ---------------- launch ----------------
extern "C" void kernel_launch(void* const* d_in, const int* in_sizes, int n_in,
                              void* d_out, int out_size) {
    const float* x    = (const float*)d_in[0];
    const int*   ei   = (const int*)d_in[1];
    const float* W1   = (const float*)d_in[2];
    const float* b1   = (const float*)d_in[3];
    const float* W2   = (const float*)d_in[4];
    const float* b2   = (const float*)d_in[5];
    const float* mask = (const float*)d_in[6];
    float*       out  = (float*)d_out;

    const int* src = ei;
    const int* dst = ei + NE;

    bool fork = (g_s != 0) && (g_e0 != 0) && (g_e1 != 0) && (g_e2 != 0);
    if (fork) fork = (cudaEventRecord(g_e0, 0) == cudaSuccess);
    if (fork) fork = (cudaStreamWaitEvent(g_s, g_e0, 0) == cudaSuccess);
    cudaStream_t cs = fork ? g_s : 0;

    // SIDE: histogram -> dinv (event e2) -> scan -> build (event e1)
    k_zero   <<<(NN + 255) / 256, 256, 0, cs>>>();
    k_hist4  <<<(NE / 4 + 255) / 256, 256, 0, cs>>>(dst);
    k_dinvC  <<<(NN + 255) / 256, 256, 0, cs>>>();
    if (fork) cudaEventRecord(g_e2, g_s);
    k_scan   <<<1, 1024, 0, cs>>>();
    k_build4 <<<(NE / 4 + 255) / 256, 256, 0, cs>>>(src, dst);
    if (fork) cudaEventRecord(g_e1, g_s);

    // MAIN: weight prep; wait dinv; gemm1
    k_prepW  <<<(NF * NH + 255) / 256, 256>>>(W1);
    k_prepW2 <<<(NH * NC + 255) / 256, 256>>>(W2);
    if (fork) cudaStreamWaitEvent(0, g_e2, 0);
    k_gemm1_mma <<<(NN + 127) / 128, 256>>>(x);

    // join: agg1 needs CSR structure
    if (fork) cudaStreamWaitEvent(0, g_e1, 0);

    k_agg1      <<<NN, 64>>>(b1, mask);
    k_gemm2_mma <<<(NN + 127) / 128, 256>>>();
    k_agg2      <<<(NN * 32 + 255) / 256, 256>>>(b2, out);
}

// round 17
// speedup vs baseline: 1.6730x; 1.3369x over previous
#include <cuda_runtime.h>
#include <cuda_fp16.h>
#include <math.h>
#include <stdint.h>

#define NN 50000
#define NE 1600000
#define NF 256
#define NH 128
#define NC 40
#define NBLK 49   // ceil(NN/1024)

// ---------------- scratch (no allocations allowed) ----------------
__device__ float g_dinv[NN];
__device__ int   g_cnt[NN];
__device__ int   g_base[NN];
__device__ int   g_cur[NN];
__device__ int   g_eidx[NE];
__device__ int   g_bsum[64];
__device__ int   g_boff[64];
__device__ __align__(16) __half g_G1h[(size_t)NN * NH];  // fp16: dinv * (X @ W1)
__device__ __align__(16) __half g_H1h[(size_t)NN * NH];  // fp16: relu(...)*mask
__device__ __align__(16) __half g_G2h[(size_t)NN * NC];  // fp16: dinv * (H1 @ W2)
__device__ __align__(16) __half g_W1f[NF * NH];          // fp16 W1 transposed: [n][k]
__device__ __align__(16) __half g_W2t[NH * NC];          // fp16 W2 transposed: [n][k]

static __device__ __forceinline__ void hmma16816_f16(float* c, uint32_t a0, uint32_t a1,
                                                     uint32_t a2, uint32_t a3,
                                                     uint32_t b0, uint32_t b1) {
    asm volatile("mma.sync.aligned.m16n8k16.row.col.f32.f16.f16.f32 "
                 "{%0,%1,%2,%3}, {%4,%5,%6,%7}, {%8,%9}, {%0,%1,%2,%3};"
                 : "+f"(c[0]), "+f"(c[1]), "+f"(c[2]), "+f"(c[3])
                 : "r"(a0), "r"(a1), "r"(a2), "r"(a3), "r"(b0), "r"(b1));
}
static __device__ __forceinline__ uint32_t pkh2(float a, float b) {
    __half2 h = __floats2half2_rn(a, b);
    return *(uint32_t*)&h;
}

// ================= SIDE-STREAM: CSR + dinv =================
__global__ void k_zero() {
    int v = blockIdx.x * 256 + threadIdx.x;
    if (v < NN) g_cnt[v] = 0;
}
__global__ void k_hist4(const int* __restrict__ dst) {
    int t = blockIdx.x * 256 + threadIdx.x;
    if (t < NE / 4) {
        int4 d = ((const int4*)dst)[t];
        atomicAdd(&g_cnt[d.x], 1);
        atomicAdd(&g_cnt[d.y], 1);
        atomicAdd(&g_cnt[d.z], 1);
        atomicAdd(&g_cnt[d.w], 1);
    }
}
__global__ void k_dinvC() {
    int v = blockIdx.x * 256 + threadIdx.x;
    if (v < NN) g_dinv[v] = rsqrtf((float)(g_cnt[v] + 1));
}
// ---- parallel exclusive scan of g_cnt -> g_base/g_cur ----
__global__ __launch_bounds__(1024) void k_bsum() {
    __shared__ int sm[1024];
    int i = blockIdx.x * 1024 + threadIdx.x;
    sm[threadIdx.x] = (i < NN) ? g_cnt[i] : 0;
    __syncthreads();
#pragma unroll
    for (int off = 512; off; off >>= 1) {
        if (threadIdx.x < off) sm[threadIdx.x] += sm[threadIdx.x + off];
        __syncthreads();
    }
    if (threadIdx.x == 0) g_bsum[blockIdx.x] = sm[0];
}
__global__ void k_bscan() {   // 1 block, 64 threads
    __shared__ int sm[64];
    int t = threadIdx.x;
    int v = (t < NBLK) ? g_bsum[t] : 0;
    sm[t] = v;
    __syncthreads();
#pragma unroll
    for (int off = 1; off < 64; off <<= 1) {
        int u = (t >= off) ? sm[t - off] : 0;
        __syncthreads();
        sm[t] += u;
        __syncthreads();
    }
    if (t < NBLK) g_boff[t] = sm[t] - v;   // exclusive
}
__global__ __launch_bounds__(1024) void k_bprefix() {
    __shared__ int sm[1024];
    int i = blockIdx.x * 1024 + threadIdx.x;
    int c = (i < NN) ? g_cnt[i] : 0;
    sm[threadIdx.x] = c;
    __syncthreads();
#pragma unroll
    for (int off = 1; off < 1024; off <<= 1) {
        int u = (threadIdx.x >= off) ? sm[threadIdx.x - off] : 0;
        __syncthreads();
        sm[threadIdx.x] += u;
        __syncthreads();
    }
    if (i < NN) {
        int base = g_boff[blockIdx.x] + sm[threadIdx.x] - c;   // exclusive
        g_base[i] = base;
        g_cur[i] = base;
    }
}
__global__ void k_build4(const int* __restrict__ src, const int* __restrict__ dst) {
    int t = blockIdx.x * 256 + threadIdx.x;
    if (t < NE / 4) {
        int4 s = ((const int4*)src)[t];
        int4 d = ((const int4*)dst)[t];
        int p0 = atomicAdd(&g_cur[d.x], 1);
        int p1 = atomicAdd(&g_cur[d.y], 1);
        int p2 = atomicAdd(&g_cur[d.z], 1);
        int p3 = atomicAdd(&g_cur[d.w], 1);
        g_eidx[p0] = s.x;
        g_eidx[p1] = s.y;
        g_eidx[p2] = s.z;
        g_eidx[p3] = s.w;
    }
}

// ---------------- weight prep (main stream) ----------------
__global__ void k_prepW(const float* __restrict__ W1) {
    int idx = blockIdx.x * 256 + threadIdx.x;
    if (idx >= NF * NH) return;
    int k = idx >> 7;
    int n = idx & 127;
    g_W1f[n * NF + k] = __float2half(W1[idx]);
}
__global__ void k_prepW2(const float* __restrict__ W2) {
    int idx = blockIdx.x * 256 + threadIdx.x;
    if (idx >= NH * NC) return;
    int k = idx / NC;
    int n = idx - k * NC;
    g_W2t[n * NH + k] = __float2half(W2[idx]);
}

// ---------------- GEMM1 (fp16 mma): G1 = dinv * (X @ W1) ----------------
#define SSTR 20
__global__ __launch_bounds__(256) void k_gemm1_mma(const float* __restrict__ x) {
    __shared__ uint32_t uA[128 * SSTR];
    __shared__ uint32_t uB[128 * SSTR];

    const int tid = threadIdx.x;
    const int w = tid >> 5;
    const int lane = tid & 31;
    const int g = lane >> 2;
    const int tig = lane & 3;
    const int row0 = blockIdx.x * 128;

    float4 pa[4];
    uint4 pb[2];

    float acc[16][4];
#pragma unroll
    for (int nt = 0; nt < 16; nt++)
#pragma unroll
        for (int i = 0; i < 4; i++) acc[nt][i] = 0.f;

#pragma unroll
    for (int q = 0; q < 4; q++) {
        int idx = tid + q * 256;
        int ar = idx >> 3, aq = idx & 7;
        int gr = min(row0 + ar, NN - 1);
        pa[q] = *(const float4*)&x[(size_t)gr * NF + 0 + aq * 4];
    }
#pragma unroll
    for (int q = 0; q < 2; q++) {
        int idx = tid + q * 256;
        int br = idx >> 2, bc = idx & 3;
        pb[q] = *(const uint4*)&g_W1f[(size_t)br * NF + 0 + bc * 8];
    }

    for (int ch = 0; ch < 8; ch++) {
        __syncthreads();
#pragma unroll
        for (int q = 0; q < 4; q++) {
            int idx = tid + q * 256;
            int ar = idx >> 3, aq = idx & 7;
            float4 v = pa[q];
            uint32_t* p = &uA[ar * SSTR + aq * 2];
            p[0] = pkh2(v.x, v.y);
            p[1] = pkh2(v.z, v.w);
        }
#pragma unroll
        for (int q = 0; q < 2; q++) {
            int idx = tid + q * 256;
            int br = idx >> 2, bc = idx & 3;
            uint32_t* p = &uB[br * SSTR + bc * 4];
            p[0] = pb[q].x; p[1] = pb[q].y; p[2] = pb[q].z; p[3] = pb[q].w;
        }
        __syncthreads();
        if (ch < 7) {
            const int kn = (ch + 1) * 32;
#pragma unroll
            for (int q = 0; q < 4; q++) {
                int idx = tid + q * 256;
                int ar = idx >> 3, aq = idx & 7;
                int gr = min(row0 + ar, NN - 1);
                pa[q] = *(const float4*)&x[(size_t)gr * NF + kn + aq * 4];
            }
#pragma unroll
            for (int q = 0; q < 2; q++) {
                int idx = tid + q * 256;
                int br = idx >> 2, bc = idx & 3;
                pb[q] = *(const uint4*)&g_W1f[(size_t)br * NF + kn + bc * 8];
            }
        }
#pragma unroll
        for (int ks = 0; ks < 2; ks++) {
            const int ko = ks * 8;
            const int ra0 = (w * 16 + g) * SSTR + tig + ko;
            const int ra1 = (w * 16 + g + 8) * SSTR + tig + ko;
            uint32_t a0 = uA[ra0],     a1 = uA[ra1];
            uint32_t a2 = uA[ra0 + 4], a3 = uA[ra1 + 4];
#pragma unroll
            for (int nt = 0; nt < 16; nt++) {
                const int rb = (nt * 8 + g) * SSTR + tig + ko;
                hmma16816_f16(acc[nt], a0, a1, a2, a3, uB[rb], uB[rb + 4]);
            }
        }
    }
    const int r0 = row0 + w * 16 + g;
    const int r1 = r0 + 8;
    const float dv0 = (r0 < NN) ? g_dinv[r0] : 0.f;
    const float dv1 = (r1 < NN) ? g_dinv[r1] : 0.f;
#pragma unroll
    for (int nt = 0; nt < 16; nt++) {
        const int col = nt * 8 + tig * 2;
        if (r0 < NN)
            *(__half2*)&g_G1h[(size_t)r0 * NH + col] =
                __floats2half2_rn(acc[nt][0] * dv0, acc[nt][1] * dv0);
        if (r1 < NN)
            *(__half2*)&g_G1h[(size_t)r1 * NH + col] =
                __floats2half2_rn(acc[nt][2] * dv1, acc[nt][3] * dv1);
    }
}

// ---------------- agg layer1: fp16 gather, fp32 accumulate, fp16 H1 out ----------------
__global__ __launch_bounds__(64) void k_agg1(const float* __restrict__ b1,
                                             const float* __restrict__ mask) {
    const int v = blockIdx.x;
    const int tid = threadIdx.x;
    const __half2* G1 = (const __half2*)g_G1h;
    float2 s0 = __half22float2(G1[(size_t)v * 64 + tid]);
    float ax0 = s0.x, ay0 = s0.y;
    float ax1 = 0.f, ay1 = 0.f, ax2 = 0.f, ay2 = 0.f, ax3 = 0.f, ay3 = 0.f;
    const int beg = g_base[v];
    const int n = g_cnt[v];
    int j = 0;
    for (; j + 4 <= n; j += 4) {
        int e0 = g_eidx[beg + j];
        int e1 = g_eidx[beg + j + 1];
        int e2 = g_eidx[beg + j + 2];
        int e3 = g_eidx[beg + j + 3];
        float2 f0 = __half22float2(G1[(size_t)e0 * 64 + tid]);
        float2 f1 = __half22float2(G1[(size_t)e1 * 64 + tid]);
        float2 f2 = __half22float2(G1[(size_t)e2 * 64 + tid]);
        float2 f3 = __half22float2(G1[(size_t)e3 * 64 + tid]);
        ax0 += f0.x; ay0 += f0.y;
        ax1 += f1.x; ay1 += f1.y;
        ax2 += f2.x; ay2 += f2.y;
        ax3 += f3.x; ay3 += f3.y;
    }
    for (; j < n; j++) {
        int e = g_eidx[beg + j];
        float2 f = __half22float2(G1[(size_t)e * 64 + tid]);
        ax0 += f.x; ay0 += f.y;
    }
    float accx = (ax0 + ax1) + (ax2 + ax3);
    float accy = (ay0 + ay1) + (ay2 + ay3);
    const float dv = g_dinv[v];
    float2 bb = *(const float2*)&b1[2 * tid];
    float2 mm = *(const float2*)&mask[(size_t)v * NH + 2 * tid];
    float hx = fmaxf(fmaf(accx, dv, bb.x), 0.f) * mm.x;
    float hy = fmaxf(fmaf(accy, dv, bb.y), 0.f) * mm.y;
    ((__half2*)g_H1h)[(size_t)v * 64 + tid] = __floats2half2_rn(hx, hy);
}

// ---------------- GEMM2 (fp16 mma): G2 = dinv * (H1 @ W2), fp16 out ----------------
__global__ __launch_bounds__(256) void k_gemm2_mma() {
    __shared__ uint32_t uA[128 * SSTR];
    __shared__ uint32_t uB[40 * SSTR];

    const int tid = threadIdx.x;
    const int w = tid >> 5;
    const int lane = tid & 31;
    const int g = lane >> 2;
    const int tig = lane & 3;
    const int row0 = blockIdx.x * 128;

    float acc[5][4];
#pragma unroll
    for (int nt = 0; nt < 5; nt++)
#pragma unroll
        for (int i = 0; i < 4; i++) acc[nt][i] = 0.f;

    for (int ch = 0; ch < 4; ch++) {
        const int k0 = ch * 32;
        __syncthreads();
#pragma unroll
        for (int q = 0; q < 2; q++) {
            int idx = tid + q * 256;
            int ar = idx >> 2, ac = idx & 3;
            int gr = min(row0 + ar, NN - 1);
            uint4 v = *(const uint4*)&g_H1h[(size_t)gr * NH + k0 + ac * 8];
            uint32_t* p = &uA[ar * SSTR + ac * 4];
            p[0] = v.x; p[1] = v.y; p[2] = v.z; p[3] = v.w;
        }
        if (tid < 160) {
            int br = tid >> 2, bc = tid & 3;
            uint4 v = *(const uint4*)&g_W2t[(size_t)br * NH + k0 + bc * 8];
            uint32_t* p = &uB[br * SSTR + bc * 4];
            p[0] = v.x; p[1] = v.y; p[2] = v.z; p[3] = v.w;
        }
        __syncthreads();
#pragma unroll
        for (int ks = 0; ks < 2; ks++) {
            const int ko = ks * 8;
            const int ra0 = (w * 16 + g) * SSTR + tig + ko;
            const int ra1 = (w * 16 + g + 8) * SSTR + tig + ko;
            uint32_t a0 = uA[ra0],     a1 = uA[ra1];
            uint32_t a2 = uA[ra0 + 4], a3 = uA[ra1 + 4];
#pragma unroll
            for (int nt = 0; nt < 5; nt++) {
                const int rb = (nt * 8 + g) * SSTR + tig + ko;
                hmma16816_f16(acc[nt], a0, a1, a2, a3, uB[rb], uB[rb + 4]);
            }
        }
    }
    const int r0 = row0 + w * 16 + g;
    const int r1 = r0 + 8;
    const float dv0 = (r0 < NN) ? g_dinv[r0] : 0.f;
    const float dv1 = (r1 < NN) ? g_dinv[r1] : 0.f;
#pragma unroll
    for (int nt = 0; nt < 5; nt++) {
        const int col = nt * 8 + tig * 2;
        if (r0 < NN)
            *(__half2*)&g_G2h[(size_t)r0 * NC + col] =
                __floats2half2_rn(acc[nt][0] * dv0, acc[nt][1] * dv0);
        if (r1 < NN)
            *(__half2*)&g_G2h[(size_t)r1 * NC + col] =
                __floats2half2_rn(acc[nt][2] * dv1, acc[nt][3] * dv1);
    }
}

// ---------------- agg layer2: fp16 gather + bias + log_softmax fused ----------------
__global__ __launch_bounds__(256) void k_agg2(const float* __restrict__ b2,
                                              float* __restrict__ out) {
    const int w = (blockIdx.x * blockDim.x + threadIdx.x) >> 5;
    const int lane = threadIdx.x & 31;
    if (w >= NN) return;
    const bool act = (lane < NC / 2);
    const __half2* G2 = (const __half2*)g_G2h;

    float ax = 0.f, ay = 0.f, cx = 0.f, cy = 0.f;
    if (act) {
        float2 f = __half22float2(G2[(size_t)w * 20 + lane]);
        ax = f.x; ay = f.y;
    }
    const int beg = g_base[w];
    const int n = g_cnt[w];
    int j = 0;
    for (; j + 2 <= n; j += 2) {
        int e0 = g_eidx[beg + j];
        int e1 = g_eidx[beg + j + 1];
        if (act) {
            float2 f0 = __half22float2(G2[(size_t)e0 * 20 + lane]);
            float2 f1 = __half22float2(G2[(size_t)e1 * 20 + lane]);
            ax += f0.x; ay += f0.y;
            cx += f1.x; cy += f1.y;
        }
    }
    if (j < n) {
        int e = g_eidx[beg + j];
        if (act) {
            float2 f = __half22float2(G2[(size_t)e * 20 + lane]);
            ax += f.x; ay += f.y;
        }
    }
    ax += cx; ay += cy;

    const float dv = g_dinv[w];
    float v0 = act ? fmaf(ax, dv, b2[2 * lane]) : -1e30f;
    float v1 = act ? fmaf(ay, dv, b2[2 * lane + 1]) : -1e30f;

    float m = fmaxf(v0, v1);
#pragma unroll
    for (int o = 16; o; o >>= 1) m = fmaxf(m, __shfl_xor_sync(0xFFFFFFFFu, m, o));
    float s = act ? (expf(v0 - m) + expf(v1 - m)) : 0.f;
#pragma unroll
    for (int o = 16; o; o >>= 1) s += __shfl_xor_sync(0xFFFFFFFFu, s, o);
    float l = m + logf(s);
    if (act) {
        const size_t rb = (size_t)w * NC;
        out[rb + 2 * lane] = v0 - l;
        out[rb + 2 * lane + 1] = v1 - l;
    }
}

// ---------------- fork-join resources (created pre-baseline in static init) ----------------
static cudaStream_t g_s = 0;
static cudaEvent_t g_e0 = 0, g_e1 = 0, g_e2 = 0;
static struct GcnInit {
    GcnInit() {
        if (cudaStreamCreateWithFlags(&g_s, cudaStreamNonBlocking) != cudaSuccess) { g_s = 0; return; }
        if (cudaEventCreateWithFlags(&g_e0, cudaEventDisableTiming) != cudaSuccess) { g_e0 = 0; return; }
        if (cudaEventCreateWithFlags(&g_e1, cudaEventDisableTiming) != cudaSuccess) { g_e1 = 0; return; }
        if (cudaEventCreateWithFlags(&g_e2, cudaEventDisableTiming) != cudaSuccess) { g_e2 = 0; }
    }
} g_gcn_init;

// ---------------- launch ----------------
extern "C" void kernel_launch(void* const* d_in, const int* in_sizes, int n_in,
                              void* d_out, int out_size) {
    const float* x    = (const float*)d_in[0];
    const int*   ei   = (const int*)d_in[1];
    const float* W1   = (const float*)d_in[2];
    const float* b1   = (const float*)d_in[3];
    const float* W2   = (const float*)d_in[4];
    const float* b2   = (const float*)d_in[5];
    const float* mask = (const float*)d_in[6];
    float*       out  = (float*)d_out;

    const int* src = ei;
    const int* dst = ei + NE;

    bool fork = (g_s != 0) && (g_e0 != 0) && (g_e1 != 0) && (g_e2 != 0);
    if (fork) fork = (cudaEventRecord(g_e0, 0) == cudaSuccess);
    if (fork) fork = (cudaStreamWaitEvent(g_s, g_e0, 0) == cudaSuccess);
    cudaStream_t cs = fork ? g_s : 0;

    // SIDE: histogram -> dinv (event e2) -> parallel scan -> build (event e1)
    k_zero    <<<(NN + 255) / 256, 256, 0, cs>>>();
    k_hist4   <<<(NE / 4 + 255) / 256, 256, 0, cs>>>(dst);
    k_dinvC   <<<(NN + 255) / 256, 256, 0, cs>>>();
    if (fork) cudaEventRecord(g_e2, g_s);
    k_bsum    <<<NBLK, 1024, 0, cs>>>();
    k_bscan   <<<1, 64, 0, cs>>>();
    k_bprefix <<<NBLK, 1024, 0, cs>>>();
    k_build4  <<<(NE / 4 + 255) / 256, 256, 0, cs>>>(src, dst);
    if (fork) cudaEventRecord(g_e1, g_s);

    // MAIN: weight prep; wait dinv; gemm1
    k_prepW  <<<(NF * NH + 255) / 256, 256>>>(W1);
    k_prepW2 <<<(NH * NC + 255) / 256, 256>>>(W2);
    if (fork) cudaStreamWaitEvent(0, g_e2, 0);
    k_gemm1_mma <<<(NN + 127) / 128, 256>>>(x);

    // join: agg1 needs CSR structure
    if (fork) cudaStreamWaitEvent(0, g_e1, 0);

    k_agg1      <<<NN, 64>>>(b1, mask);
    k_gemm2_mma <<<(NN + 127) / 128, 256>>>();
    k_agg2      <<<(NN * 32 + 255) / 256, 256>>>(b2, out);
}